// round 12
// baseline (speedup 1.0000x reference)
#include <cuda_runtime.h>
#include <stdint.h>

#define H 2048
#define W 2048
#define KS 11
#define PS 10
#define PAD 5
#define HO 205                 // conv output: floor((2048+10-11)/10)+1
#define OUT 2255               // 205 * (PS+1)
#define CELLS (HO*HO)
#define BANDS (3*HO)           // (channel, oh) output bands of 11 rows

// Intermediate per-cell result: [3][HO][HO] (+pad for safe over-read)
__device__ float g_mid[3 * HO * HO + 8];

__device__ __forceinline__ unsigned smem_u32(const void* p) {
    unsigned a;
    asm("{ .reg .u64 t; cvta.to.shared.u64 t, %1; cvt.u32.u64 %0, t; }"
        : "=r"(a) : "l"(p));
    return a;
}

// ---------------------------------------------------------------------------
// Kernel 1: one warp per output cell (R10/R11 body — best measured class).
// ---------------------------------------------------------------------------
__global__ void __launch_bounds__(256) cell_kernel(const float* __restrict__ rgb) {
    const int wid = (blockIdx.x * blockDim.x + threadIdx.x) >> 5;
    if (wid >= CELLS) return;
    const int lane = threadIdx.x & 31;

    const int oh = wid / HO;
    const int ow = wid - oh * HO;
    const int y0 = oh * PS - PAD;
    const int x0 = ow * PS - PAD;
    const bool border = (oh == 0) | (ow == 0);   // 409 of 42025, warp-uniform

    const float* __restrict__ rp = rgb;
    const float* __restrict__ gp = rgb + H * W;
    const float* __restrict__ bp = rgb + 2 * H * W;

    int off[4];
    bool act[4];
    act[0] = true; act[1] = true; act[2] = true; act[3] = (lane < 25);
#pragma unroll
    for (int t = 0; t < 4; t++) {
        int p = lane + t * 32;
        if (t == 3) p = p > 120 ? 120 : p;       // dup load, masked later
        const int dy = p / KS;
        const int dx = p - dy * KS;
        off[t] = (y0 + dy) * W + (x0 + dx);
        if (border)
            act[t] = act[t] && (y0 + dy >= 0) && (x0 + dx >= 0);
    }

    // Batch ALL loads before any consumer (MLP=12 — measured critical).
    float rv[4], gv[4], bv[4];
    if (!border) {
#pragma unroll
        for (int t = 0; t < 4; t++) rv[t] = __ldg(rp + off[t]);
#pragma unroll
        for (int t = 0; t < 4; t++) gv[t] = __ldg(gp + off[t]);
#pragma unroll
        for (int t = 0; t < 4; t++) bv[t] = __ldg(bp + off[t]);
    } else {
#pragma unroll
        for (int t = 0; t < 4; t++) rv[t] = act[t] ? __ldg(rp + off[t]) : 0.0f;
#pragma unroll
        for (int t = 0; t < 4; t++) gv[t] = act[t] ? __ldg(gp + off[t]) : 0.0f;
#pragma unroll
        for (int t = 0; t < 4; t++) bv[t] = act[t] ? __ldg(bp + off[t]) : 0.0f;
    }

    // Bin + packed histogram (8-bit counters; totals <=121: carry-free).
    int bn[4];
    unsigned long long hlo = 0ULL, hhi = 0ULL;
#pragma unroll
    for (int t = 0; t < 4; t++) {
        const float s = __fadd_rn(__fadd_rn(rv[t], gv[t]), bv[t]);
        const int bi = (int)(__fmul_rn(s, 0.020833334f));   // 1/48 rn
        bn[t] = act[t] ? bi : 16;                            // 16 = dead
        if (act[t]) {
            const unsigned long long inc = 1ULL << ((bi & 7) * 8);
            if (bi < 8) hlo += inc; else hhi += inc;
        }
    }

    const unsigned h0 = __reduce_add_sync(0xffffffffu, (unsigned)hlo);
    const unsigned h1 = __reduce_add_sync(0xffffffffu, (unsigned)(hlo >> 32));
    const unsigned h2 = __reduce_add_sync(0xffffffffu, (unsigned)hhi);
    const unsigned h3 = __reduce_add_sync(0xffffffffu, (unsigned)(hhi >> 32));

    // Lane-parallel argmax; ties -> smaller bin (jnp.argmax first-max).
    const int b = lane & 15;
    const unsigned hw = (b < 8) ? ((b < 4) ? h0 : h1) : ((b < 12) ? h2 : h3);
    const unsigned cnt = (hw >> ((b & 3) * 8)) & 0xFFu;
    const unsigned key = (cnt << 4) | (unsigned)(15 - b);
    const unsigned kmax = __reduce_max_sync(0xffffffffu, key);
    const int amax = 15 - (int)(kmax & 15u);
    const float cm = (float)(kmax >> 4);

    // Masked channel sums in 16.16 fixed point (sum < 2^31; err ~1e-7 rel).
    int sri = 0, sgi = 0, sbi = 0;
#pragma unroll
    for (int t = 0; t < 4; t++) {
        if (bn[t] == amax) {
            sri += (int)(rv[t] * 65536.0f);
            sgi += (int)(gv[t] * 65536.0f);
            sbi += (int)(bv[t] * 65536.0f);
        }
    }
    const unsigned sru = __reduce_add_sync(0xffffffffu, (unsigned)sri);
    const unsigned sgu = __reduce_add_sync(0xffffffffu, (unsigned)sgi);
    const unsigned sbu = __reduce_add_sync(0xffffffffu, (unsigned)sbi);

    if (lane == 0) {
        const float inv = __fmul_rn(__frcp_rn(cm), 1.52587890625e-05f);
        g_mid[wid]               = __fmul_rn((float)sru, inv);
        g_mid[wid + HO * HO]     = __fmul_rn((float)sgu, inv);
        g_mid[wid + 2 * HO * HO] = __fmul_rn((float)sbu, inv);
    }
}

// ---------------------------------------------------------------------------
// Kernel 2: upsample via TMA bulk stores, 2 blocks per band (rows 0-5 / 6-10).
// Each block builds the 4 shifted templates directly (sbuf[a][x] = T[x+a],
// one div + two L1-hot LDGs per x), then threads 64..64+nrows each issue,
// commit and wait their OWN row's ~9KB bulk store (independent bulk groups).
// Heads/tails (<=3+3 floats/row) are scalar fixups by threads 0..47.
// ---------------------------------------------------------------------------
__global__ void __launch_bounds__(256) upsample_kernel(float* __restrict__ out) {
    __shared__ __align__(16) float sbuf[5][2264];   // 4 shifts + zero row

    const int bx = blockIdx.x;                      // 0 .. 2*BANDS-1
    const int band = bx >> 1;
    const int half = bx & 1;
    const int c = band / HO;
    const int oh = band - c * HO;
    const int r0 = half ? 6 : 0;
    const int r1 = half ? 11 : 6;
    const int tid = threadIdx.x;

    const float* __restrict__ midc = g_mid + c * (HO * HO) + oh * HO;

    // Zero buffer only needed by the half that owns the pad row (row 10)
    if (half)
        for (int x = tid; x < 2264; x += 256) sbuf[4][x] = 0.0f;

    // Shifted templates: sbuf[a][x] = T[x+a], T[y] = (y%11<10) ? mid[y/11] : 0
    for (int x = tid; x < 2264; x += 256) {
        const unsigned o0 = (unsigned)x / 11u;
        const int j0 = x - (int)o0 * 11;            // 0..10
        const float m0 = __ldg(midc + o0);          // g_mid padded: safe o0<=206
        const float m1 = __ldg(midc + o0 + 1);
#pragma unroll
        for (int a = 0; a < 4; a++) {
            const int j = j0 + a;                   // <= 13
            sbuf[a][x] = (j < 10) ? m0 : ((j == 10) ? 0.0f : m1);
        }
    }
    __syncthreads();
    asm volatile("fence.proxy.async.shared::cta;" ::: "memory");

    const size_t base0 = ((size_t)c * OUT + (size_t)oh * 11) * (size_t)OUT;

    // Scalar head/tail fixups for this half's rows (nf == 2252 always)
    if (tid < 48) {
        const float m0 = __ldg(midc);
        const float mL = __ldg(midc + 204);
        const int r = r0 + (tid >> 3);              // row
        const int k = tid & 7;
        if (r < r1) {
            const size_t gb = base0 + (size_t)r * OUT;
            const int hr = (int)((4u - ((unsigned)gb & 3u)) & 3u);
            const bool live = (r < 10);
            if (k < 4) {
                if (k < hr) out[gb + k] = live ? m0 : 0.0f;  // x<=2: ow=0,j<10
            } else {
                const int x = hr + 2252 + (k - 4);           // j = 8,9,10
                if (x < OUT) out[gb + x] = (live && x < 2254) ? mL : 0.0f;
            }
        }
    }

    // TMA bulk stores: one row per thread (warp 2), independent bulk groups
    if (tid >= 64 && tid < 64 + (r1 - r0)) {
        const int r = r0 + (tid - 64);
        const size_t gb = base0 + (size_t)r * OUT;
        const int hr = (int)((4u - ((unsigned)gb & 3u)) & 3u);
        const int bufi = (r < 10) ? hr : 4;
        float* gdst = out + gb + (size_t)hr;
        const unsigned saddr = smem_u32(&sbuf[bufi][0]);
        asm volatile(
            "cp.async.bulk.global.shared::cta.bulk_group [%0], [%1], %2;"
            :: "l"(gdst), "r"(saddr), "n"(9008) : "memory");
        asm volatile("cp.async.bulk.commit_group;" ::: "memory");
        asm volatile("cp.async.bulk.wait_group 0;" ::: "memory");
    }
}

extern "C" void kernel_launch(void* const* d_in, const int* in_sizes, int n_in,
                              void* d_out, int out_size) {
    const float* rgb = (const float*)d_in[0];
    float* out = (float*)d_out;

    const int blocks1 = (CELLS + 7) / 8;       // one warp per cell, 8/block
    cell_kernel<<<blocks1, 256>>>(rgb);

    upsample_kernel<<<2 * BANDS, 256>>>(out);  // 2 blocks per 11-row band
}